// round 8
// baseline (speedup 1.0000x reference)
#include <cuda_runtime.h>
#include <cuda_bf16.h>
#include <stdint.h>
#include <math.h>

// Problem constants: B=4, C=64, H=W=64, P=4096.
#define BATCH 4
#define CCH   64
#define PPIX  4096
#define LOG2E 1.4426950408889634f
#define CROSS_SCALE 3.814697265625e-06f   // 1/262144

// ---------------------------------------------------------------------------
// Device scratch. bf16 split x = hi + lo; int8 mirrors for cross-term IMMA.
// ---------------------------------------------------------------------------
__device__ __nv_bfloat16 g_Qh[BATCH * PPIX * CCH];  // Y boxsum  [b][p][c]
__device__ __nv_bfloat16 g_Ql[BATCH * PPIX * CCH];
__device__ __nv_bfloat16 g_Kh[BATCH * PPIX * CCH];  // K-hat     [b][p][c]
__device__ __nv_bfloat16 g_Kl[BATCH * PPIX * CCH];
__device__ char          g_Q8h[BATCH * PPIX * CCH]; // round(Yh*4)
__device__ char          g_Q8l[BATCH * PPIX * CCH]; // round(Yl*2048)
__device__ char          g_K8 [BATCH * PPIX * 128]; // [0..63]=round(Kl*65536), [64..127]=round(Kh*128)
__device__ float         g_m [BATCH * PPIX];        // |Y_q| (softmax max bound)

// ---------------------------------------------------------------------------
// helpers (baseline PTX only)
// ---------------------------------------------------------------------------
__device__ __forceinline__ uint32_t smem_u32(const void* p) {
    uint32_t a;
    asm("{ .reg .u64 t; cvta.to.shared.u64 t, %1; cvt.u32.u64 %0, t; }" : "=r"(a) : "l"(p));
    return a;
}
__device__ __forceinline__ uint32_t lds32(uint32_t a) {
    uint32_t v; asm volatile("ld.shared.b32 %0, [%1];" : "=r"(v) : "r"(a)); return v;
}
__device__ __forceinline__ void ldsm4t(uint32_t* r, uint32_t addr) {
    asm volatile("ldmatrix.sync.aligned.m8n8.x4.trans.shared.b16 {%0,%1,%2,%3}, [%4];"
        : "=r"(r[0]), "=r"(r[1]), "=r"(r[2]), "=r"(r[3]) : "r"(addr));
}
__device__ __forceinline__ void mma16816(float* d, const uint32_t* a, uint32_t b0, uint32_t b1) {
    asm volatile(
        "mma.sync.aligned.m16n8k16.row.col.f32.bf16.bf16.f32 "
        "{%0,%1,%2,%3}, {%4,%5,%6,%7}, {%8,%9}, {%0,%1,%2,%3};"
        : "+f"(d[0]), "+f"(d[1]), "+f"(d[2]), "+f"(d[3])
        : "r"(a[0]), "r"(a[1]), "r"(a[2]), "r"(a[3]), "r"(b0), "r"(b1));
}
__device__ __forceinline__ void imma16832(int* d, const uint32_t* a, uint32_t b0, uint32_t b1) {
    asm volatile(
        "mma.sync.aligned.m16n8k32.row.col.s32.s8.s8.s32 "
        "{%0,%1,%2,%3}, {%4,%5,%6,%7}, {%8,%9}, {%0,%1,%2,%3};"
        : "+r"(d[0]), "+r"(d[1]), "+r"(d[2]), "+r"(d[3])
        : "r"(a[0]), "r"(a[1]), "r"(a[2]), "r"(a[3]), "r"(b0), "r"(b1));
}
__device__ __forceinline__ float ex2(float x) {
    float r; asm("ex2.approx.ftz.f32 %0, %1;" : "=f"(r) : "f"(x)); return r;
}
__device__ __forceinline__ int f2s8(float x) {
    int r; asm("cvt.rni.sat.s8.f32 %0, %1;" : "=r"(r) : "f"(x)); return r;
}
__device__ __forceinline__ void split_bf16(float x, __nv_bfloat16& h, __nv_bfloat16& l) {
    h = __float2bfloat16_rn(x);
    l = __float2bfloat16_rn(x - __bfloat162float(h));
}
__device__ __forceinline__ void split2(float p0, float p1, uint32_t& hp, uint32_t& lp) {
    __nv_bfloat16 h0, l0, h1, l1;
    split_bf16(p0, h0, l0);
    split_bf16(p1, h1, l1);
    hp = (uint32_t)__bfloat16_as_ushort(h0) | ((uint32_t)__bfloat16_as_ushort(h1) << 16);
    lp = (uint32_t)__bfloat16_as_ushort(l0) | ((uint32_t)__bfloat16_as_ushort(l1) << 16);
}

// smem tiles per buffer: bf16 Kh [128][144B], bf16 Kl, int8 K-concat [128][144B]
#define KPITCH    144
#define TILE_H    18432            // 128 * 144
#define BUF_BYTES 55296            // Kh + Kl + K8
#define SMEM_TOTAL 110592          // two buffers (2 CTAs/SM: 221KB < 228KB)

__device__ __forceinline__ void load_tile(uint32_t dbuf,
                                          const __nv_bfloat16* gKh,
                                          const __nv_bfloat16* gKl,
                                          const char* gK8,
                                          int k0, int t) {
    #pragma unroll
    for (int c = 0; c < 4; ++c) {
        int idx = t + 256 * c;                 // 0..1023
        int row = idx >> 3, ch = idx & 7;
        uint32_t d = dbuf + row * KPITCH + ch * 16;
        const void* sh = gKh + (size_t)(k0 + row) * CCH + ch * 8;
        const void* sl = gKl + (size_t)(k0 + row) * CCH + ch * 8;
        const void* s8 = gK8 + (size_t)(k0 + row) * 128 + ch * 16;
        asm volatile("cp.async.cg.shared.global [%0], [%1], 16;" :: "r"(d), "l"(sh));
        asm volatile("cp.async.cg.shared.global [%0], [%1], 16;" :: "r"(d + TILE_H), "l"(sl));
        asm volatile("cp.async.cg.shared.global [%0], [%1], 16;" :: "r"(d + 2 * TILE_H), "l"(s8));
    }
}

// ---------------------------------------------------------------------------
// prep: one CTA per (h row, batch); emits bf16 splits + int8 mirrors.
// ---------------------------------------------------------------------------
#define VPITCH 67
__global__ void __launch_bounds__(256) prep_kernel(const float* __restrict__ f) {
    const int b = blockIdx.y;
    const int h = blockIdx.x;
    const int t = threadIdx.x;

    __shared__ float vs[CCH * VPITCH];
    __shared__ float fs[CCH * VPITCH];
    __shared__ float rf[4][64], ry[4][64];
    __shared__ float sinv[64];

    const float* fb = f + (size_t)b * CCH * PPIX + h * 64;

    #pragma unroll
    for (int i = t; i < CCH * 64; i += 256) {
        int c = i >> 6, w = i & 63;
        const float* base = fb + (size_t)c * PPIX + w;
        float mid = base[0];
        float top = (h > 0)  ? base[-64] : 0.f;
        float bot = (h < 63) ? base[64]  : 0.f;
        vs[c * VPITCH + w + 1] = top + mid + bot;
        fs[c * VPITCH + w + 1] = mid;
    }
    if (t < CCH) { vs[t * VPITCH] = 0.f; vs[t * VPITCH + 65] = 0.f; }
    __syncthreads();

    {
        const int w = t & 63, s = t >> 6;
        float fsq = 0.f, ysq = 0.f;
        #pragma unroll
        for (int cc = 0; cc < 16; ++cc) {
            int c = s * 16 + cc;
            float fv = fs[c * VPITCH + w + 1];
            float yv = vs[c * VPITCH + w] + vs[c * VPITCH + w + 1] + vs[c * VPITCH + w + 2];
            fsq = fmaf(fv, fv, fsq);
            ysq = fmaf(yv, yv, ysq);
        }
        rf[s][w] = fsq;
        ry[s][w] = ysq;
    }
    __syncthreads();
    if (t < 64) {
        float F = rf[0][t] + rf[1][t] + rf[2][t] + rf[3][t];
        float Y = ry[0][t] + ry[1][t] + ry[2][t] + ry[3][t];
        sinv[t] = 1.f / (sqrtf(F) + 1e-8f);
        g_m[b * PPIX + h * 64 + t] = sqrtf(Y);
    }
    __syncthreads();

    const int c = t & 63, s = t >> 6;
    #pragma unroll
    for (int it = 0; it < 16; ++it) {
        const int w = s * 16 + it;
        const float yv = vs[c * VPITCH + w] + vs[c * VPITCH + w + 1] + vs[c * VPITCH + w + 2];
        const float kv = fs[c * VPITCH + w + 1] * sinv[w];
        const size_t rowbase = ((size_t)(b * PPIX + h * 64 + w)) * CCH + c;
        __nv_bfloat16 hh, ll;
        split_bf16(yv, hh, ll);
        g_Qh[rowbase] = hh; g_Ql[rowbase] = ll;
        g_Q8h[rowbase] = (char)f2s8(__bfloat162float(hh) * 4.f);
        g_Q8l[rowbase] = (char)f2s8(__bfloat162float(ll) * 2048.f);
        split_bf16(kv, hh, ll);
        g_Kh[rowbase] = hh; g_Kl[rowbase] = ll;
        const size_t k8base = ((size_t)(b * PPIX + h * 64 + w)) * 128 + c;
        g_K8[k8base]      = (char)f2s8(__bfloat162float(ll) * 65536.f);
        g_K8[k8base + 64] = (char)f2s8(__bfloat162float(hh) * 128.f);
    }
}

// ---------------------------------------------------------------------------
// attn v5: q-tile 64, 8 warps = 4(qi) x 2(kj), 2 CTAs/SM.
// S = Qh*Kh (bf16, 32 HMMA) + cross [Qh8|Ql8]*[Kl8|Kh8] (int8, 32 IMMA).
// PV = 3 bf16 passes (96 HMMA) — peaked attention needs full P/V lo terms.
// ---------------------------------------------------------------------------
__global__ void __launch_bounds__(256, 2) attn_kernel(float* __restrict__ out) {
    extern __shared__ char smem[];
    const uint32_t sb = smem_u32(smem);

    const int b    = blockIdx.y;
    const int q0   = blockIdx.x * 64;
    const int t    = threadIdx.x;
    const int lane = t & 31;
    const int wid  = t >> 5;
    const int qi   = wid >> 1, kj = wid & 1;
    const int qo   = qi * 16,  ko = kj * 64;
    const int g    = lane >> 2, tq = lane & 3;

    // ---- persistent Q A-frags: bf16 hi + int8 concat, + max bounds ----
    uint32_t qa[4][4];
    {
        const __nv_bfloat16* r0 = g_Qh + (size_t)(b * PPIX + q0 + qo + g) * CCH;
        const __nv_bfloat16* r8 = r0 + 8 * CCH;
        #pragma unroll
        for (int s = 0; s < 4; ++s) {
            int c0 = 16 * s + 2 * tq;
            qa[s][0] = *(const uint32_t*)(r0 + c0);
            qa[s][1] = *(const uint32_t*)(r8 + c0);
            qa[s][2] = *(const uint32_t*)(r0 + c0 + 8);
            qa[s][3] = *(const uint32_t*)(r8 + c0 + 8);
        }
    }
    uint32_t qa8[4][4];
    {
        #pragma unroll
        for (int kb = 0; kb < 4; ++kb) {
            const char* src = (kb < 2) ? g_Q8h : g_Q8l;
            const char* r0 = src + (size_t)(b * PPIX + q0 + qo + g) * CCH + (kb & 1) * 32 + 4 * tq;
            const char* r8 = r0 + 8 * CCH;
            qa8[kb][0] = *(const uint32_t*)(r0);
            qa8[kb][1] = *(const uint32_t*)(r8);
            qa8[kb][2] = *(const uint32_t*)(r0 + 16);
            qa8[kb][3] = *(const uint32_t*)(r8 + 16);
        }
    }
    float mk[2];
    mk[0] = g_m[b * PPIX + q0 + qo + g] * LOG2E;
    mk[1] = g_m[b * PPIX + q0 + qo + 8 + g] * LOG2E;

    float oacc[8][4];
    #pragma unroll
    for (int n = 0; n < 8; ++n)
        #pragma unroll
        for (int r = 0; r < 4; ++r) oacc[n][r] = 0.f;
    float lsum[2] = {0.f, 0.f};

    const __nv_bfloat16* gKh = g_Kh + (size_t)b * PPIX * CCH;
    const __nv_bfloat16* gKl = g_Kl + (size_t)b * PPIX * CCH;
    const char*          gK8 = g_K8 + (size_t)b * PPIX * 128;

    load_tile(sb, gKh, gKl, gK8, 0, t);
    asm volatile("cp.async.commit_group;" ::: "memory");

    const uint32_t laneoff = (uint32_t)(((lane & 7) + 8 * ((lane >> 3) & 1)) * KPITCH
                                        + (lane >> 4) * 16);

    for (int kt = 0; kt < 32; ++kt) {
        __syncthreads();
        if (kt + 1 < 32)
            load_tile(sb + ((kt + 1) & 1) * BUF_BYTES, gKh, gKl, gK8, (kt + 1) * 128, t);
        asm volatile("cp.async.commit_group;" ::: "memory");
        asm volatile("cp.async.wait_group 1;" ::: "memory");
        __syncthreads();

        const uint32_t aH = sb + (uint32_t)(kt & 1) * BUF_BYTES;
        const uint32_t aL = aH + TILE_H;
        const uint32_t aI = aH + 2 * TILE_H;

        // ---- S hi: Qh.Kh (bf16) ----
        float sacc[8][4];
        #pragma unroll
        for (int j = 0; j < 8; ++j)
            #pragma unroll
            for (int r = 0; r < 4; ++r) sacc[j][r] = 0.f;

        #pragma unroll
        for (int s = 0; s < 4; ++s) {
            #pragma unroll
            for (int jg = 0; jg < 2; ++jg) {
                uint32_t bh[4][2];
                #pragma unroll
                for (int j4 = 0; j4 < 4; ++j4) {
                    const int j = jg * 4 + j4;
                    const uint32_t o = (uint32_t)((ko + 8 * j + g) * KPITCH + 4 * tq + 32 * s);
                    bh[j4][0] = lds32(aH + o);
                    bh[j4][1] = lds32(aH + o + 16);
                }
                #pragma unroll
                for (int j4 = 0; j4 < 4; ++j4)
                    mma16816(sacc[jg * 4 + j4], qa[s], bh[j4][0], bh[j4][1]);
            }
        }

        // ---- S cross: [Qh8|Ql8].[Kl8|Kh8] (int8 IMMA, k=128) ----
        #pragma unroll
        for (int j = 0; j < 8; ++j) {
            int icc[4] = {0, 0, 0, 0};
            const uint32_t rowb = aI + (uint32_t)((ko + 8 * j + g) * KPITCH + 4 * tq);
            #pragma unroll
            for (int kb = 0; kb < 4; ++kb) {
                uint32_t b0 = lds32(rowb + kb * 32);
                uint32_t b1 = lds32(rowb + kb * 32 + 16);
                imma16832(icc, qa8[kb], b0, b1);
            }
            #pragma unroll
            for (int r = 0; r < 4; ++r)
                sacc[j][r] = fmaf(__int2float_rn(icc[r]), CROSS_SCALE, sacc[j][r]);
        }

        // ---- softmax (static max) + split-pack P (hi/lo bf16) ----
        uint32_t pah[4][4], pal[4][4];
        #pragma unroll
        for (int j = 0; j < 8; ++j) {
            float p0 = ex2(fmaf(sacc[j][0], LOG2E, -mk[0]));
            float p1 = ex2(fmaf(sacc[j][1], LOG2E, -mk[0]));
            float p2 = ex2(fmaf(sacc[j][2], LOG2E, -mk[1]));
            float p3 = ex2(fmaf(sacc[j][3], LOG2E, -mk[1]));
            lsum[0] += p0 + p1;
            lsum[1] += p2 + p3;
            uint32_t hp01, lp01, hp23, lp23;
            split2(p0, p1, hp01, lp01);
            split2(p2, p3, hp23, lp23);
            const int s2 = j >> 1, r = (j & 1) * 2;
            pah[s2][r]     = hp01;
            pah[s2][r + 1] = hp23;
            pal[s2][r]     = lp01;
            pal[s2][r + 1] = lp23;
        }

        // ---- O += Ph*Vh + Pl*Vh + Ph*Vl (bf16) ----
        #pragma unroll
        for (int s2 = 0; s2 < 4; ++s2) {
            const uint32_t base = (uint32_t)((ko + 16 * s2) * KPITCH) + laneoff;
            #pragma unroll
            for (int jpg = 0; jpg < 2; ++jpg) {
                uint32_t bh0[4], bh1[4], bl0[4], bl1[4];
                ldsm4t(bh0, aH + base + (jpg * 2 + 0) * 32);
                ldsm4t(bh1, aH + base + (jpg * 2 + 1) * 32);
                ldsm4t(bl0, aL + base + (jpg * 2 + 0) * 32);
                ldsm4t(bl1, aL + base + (jpg * 2 + 1) * 32);
                const int jpA = jpg * 2, jpB = jpg * 2 + 1;
                mma16816(oacc[2 * jpA],     pah[s2], bh0[0], bh0[1]);
                mma16816(oacc[2 * jpA + 1], pah[s2], bh0[2], bh0[3]);
                mma16816(oacc[2 * jpB],     pah[s2], bh1[0], bh1[1]);
                mma16816(oacc[2 * jpB + 1], pah[s2], bh1[2], bh1[3]);
                mma16816(oacc[2 * jpA],     pal[s2], bh0[0], bh0[1]);
                mma16816(oacc[2 * jpA + 1], pal[s2], bh0[2], bh0[3]);
                mma16816(oacc[2 * jpB],     pal[s2], bh1[0], bh1[1]);
                mma16816(oacc[2 * jpB + 1], pal[s2], bh1[2], bh1[3]);
                mma16816(oacc[2 * jpA],     pah[s2], bl0[0], bl0[1]);
                mma16816(oacc[2 * jpA + 1], pah[s2], bl0[2], bl0[3]);
                mma16816(oacc[2 * jpB],     pah[s2], bl1[0], bl1[1]);
                mma16816(oacc[2 * jpB + 1], pah[s2], bl1[2], bl1[3]);
            }
        }
    }

    // ---- epilogue ----
    #pragma unroll
    for (int h = 0; h < 2; ++h) {
        lsum[h] += __shfl_xor_sync(0xffffffffu, lsum[h], 1);
        lsum[h] += __shfl_xor_sync(0xffffffffu, lsum[h], 2);
    }

    float* redO = (float*)smem;                    // [4 qi][32 lanes][33]
    float* redL = (float*)(smem + 17408);          // [64] row lsums
    float* stg  = (float*)(smem + 36864);          // [64 c][68 q]

    if (kj == 1) {
        float* dst = redO + (qi * 32 + lane) * 33;
        #pragma unroll
        for (int n = 0; n < 8; ++n)
            #pragma unroll
            for (int r = 0; r < 4; ++r)
                dst[n * 4 + r] = oacc[n][r];
        if (tq == 0) {
            redL[qi * 16 + g]     = lsum[0];
            redL[qi * 16 + 8 + g] = lsum[1];
        }
    }
    __syncthreads();

    if (kj == 0) {
        const float* src = redO + (qi * 32 + lane) * 33;
        float inv[2];
        inv[0] = 1.f / (lsum[0] + redL[qi * 16 + g]);
        inv[1] = 1.f / (lsum[1] + redL[qi * 16 + 8 + g]);
        #pragma unroll
        for (int n = 0; n < 8; ++n)
            #pragma unroll
            for (int r = 0; r < 4; ++r) {
                float v = (oacc[n][r] + src[n * 4 + r]) * inv[r >> 1];
                int q = qo + g + ((r & 2) ? 8 : 0);
                int c = 8 * n + 2 * tq + (r & 1);
                stg[c * 68 + q] = v;
            }
    }
    __syncthreads();

    float* ob = out + (size_t)b * CCH * PPIX;
    #pragma unroll
    for (int it = 0; it < 4; ++it) {
        int i = t + 256 * it;
        int row = i >> 4, f4 = i & 15;
        float4 v = *(const float4*)(stg + row * 68 + f4 * 4);
        *(float4*)(ob + row * PPIX + q0 + 4 * f4) = v;
    }
}

// ---------------------------------------------------------------------------
extern "C" void kernel_launch(void* const* d_in, const int* in_sizes, int n_in,
                              void* d_out, int out_size) {
    const float* f = (const float*)d_in[0];   // foreground [4,64,64,64] fp32
    float* out = (float*)d_out;               // [4,64,64,64] fp32

    prep_kernel<<<dim3(64, 4), 256>>>(f);

    cudaFuncSetAttribute(attn_kernel, cudaFuncAttributeMaxDynamicSharedMemorySize, SMEM_TOTAL);
    attn_kernel<<<dim3(64, 4), 256, SMEM_TOTAL>>>(out);
}

// round 10
// speedup vs baseline: 2.2869x; 2.2869x over previous
#include <cuda_runtime.h>
#include <cuda_fp16.h>
#include <stdint.h>
#include <math.h>

// Problem constants: B=4, C=64, H=W=64, P=4096.
#define BATCH 4
#define CCH   64
#define PPIX  4096
#define LOG2E 1.4426950408889634f
#define PSH   14.0f                 // pack scale: p' = 2^(s*log2e - M + 14) <= 2^14
#define KLSCALE 256.0f
#define KLINV  0.00390625f

// ---------------------------------------------------------------------------
// Device scratch. fp16 split x = hi + lo (~22 bits). Kl stored *256 so its
// elements sit in fp16 normal range (HMMA denormal-input insurance).
// ---------------------------------------------------------------------------
__device__ __half g_Qh[BATCH * PPIX * CCH];  // Y boxsum  [b][p][c]
__device__ __half g_Ql[BATCH * PPIX * CCH];
__device__ __half g_Kh[BATCH * PPIX * CCH];  // K-hat     [b][p][c]  (also V)
__device__ __half g_Kl[BATCH * PPIX * CCH];  // (K - Kh) * 256

// ---------------------------------------------------------------------------
// helpers (baseline PTX only: mma.sync / ldmatrix / cp.async)
// ---------------------------------------------------------------------------
__device__ __forceinline__ uint32_t smem_u32(const void* p) {
    uint32_t a;
    asm("{ .reg .u64 t; cvta.to.shared.u64 t, %1; cvt.u32.u64 %0, t; }" : "=r"(a) : "l"(p));
    return a;
}
__device__ __forceinline__ uint32_t lds32(uint32_t a) {
    uint32_t v; asm volatile("ld.shared.b32 %0, [%1];" : "=r"(v) : "r"(a)); return v;
}
__device__ __forceinline__ void ldsm4t(uint32_t* r, uint32_t addr) {
    asm volatile("ldmatrix.sync.aligned.m8n8.x4.trans.shared.b16 {%0,%1,%2,%3}, [%4];"
        : "=r"(r[0]), "=r"(r[1]), "=r"(r[2]), "=r"(r[3]) : "r"(addr));
}
__device__ __forceinline__ void mma16816(float* d, const uint32_t* a, uint32_t b0, uint32_t b1) {
    asm volatile(
        "mma.sync.aligned.m16n8k16.row.col.f32.f16.f16.f32 "
        "{%0,%1,%2,%3}, {%4,%5,%6,%7}, {%8,%9}, {%0,%1,%2,%3};"
        : "+f"(d[0]), "+f"(d[1]), "+f"(d[2]), "+f"(d[3])
        : "r"(a[0]), "r"(a[1]), "r"(a[2]), "r"(a[3]), "r"(b0), "r"(b1));
}
__device__ __forceinline__ float ex2(float x) {
    float r; asm("ex2.approx.ftz.f32 %0, %1;" : "=f"(r) : "f"(x)); return r;
}
__device__ __forceinline__ void split_h16(float x, __half& h, __half& l) {
    h = __float2half_rn(x);
    l = __float2half_rn(x - __half2float(h));
}

// K tile smem geometry: [128 k][64 c] fp16, row pitch 144B (128B data + 16B pad)
#define KPITCH    144
#define TILE_H    18432            // 128 * 144
#define BUF_BYTES 36864            // hi + lo
#define SMEM_TOTAL 73728           // two buffers (2 CTAs/SM -> 144KB/SM)

__device__ __forceinline__ void load_tile(uint32_t dbuf,
                                          const __half* gKh,
                                          const __half* gKl,
                                          int k0, int t) {
    #pragma unroll
    for (int c = 0; c < 4; ++c) {
        int idx = t + 256 * c;                 // 0..1023
        int row = idx >> 3, ch = idx & 7;
        uint32_t d = dbuf + row * KPITCH + ch * 16;
        const void* sh = gKh + (size_t)(k0 + row) * CCH + ch * 8;
        const void* sl = gKl + (size_t)(k0 + row) * CCH + ch * 8;
        asm volatile("cp.async.cg.shared.global [%0], [%1], 16;" :: "r"(d), "l"(sh));
        asm volatile("cp.async.cg.shared.global [%0], [%1], 16;" :: "r"(d + TILE_H), "l"(sl));
    }
}

// ---------------------------------------------------------------------------
// prep: one CTA per (h row, batch); emits fp16 hi/lo splits (Kl scaled x256).
// ---------------------------------------------------------------------------
#define VPITCH 67
__global__ void __launch_bounds__(256) prep_kernel(const float* __restrict__ f) {
    const int b = blockIdx.y;
    const int h = blockIdx.x;
    const int t = threadIdx.x;

    __shared__ float vs[CCH * VPITCH];
    __shared__ float fs[CCH * VPITCH];
    __shared__ float rf[4][64];
    __shared__ float sinv[64];

    const float* fb = f + (size_t)b * CCH * PPIX + h * 64;

    #pragma unroll
    for (int i = t; i < CCH * 64; i += 256) {
        int c = i >> 6, w = i & 63;
        const float* base = fb + (size_t)c * PPIX + w;
        float mid = base[0];
        float top = (h > 0)  ? base[-64] : 0.f;
        float bot = (h < 63) ? base[64]  : 0.f;
        vs[c * VPITCH + w + 1] = top + mid + bot;
        fs[c * VPITCH + w + 1] = mid;
    }
    if (t < CCH) { vs[t * VPITCH] = 0.f; vs[t * VPITCH + 65] = 0.f; }
    __syncthreads();

    {
        const int w = t & 63, s = t >> 6;
        float fsq = 0.f;
        #pragma unroll
        for (int cc = 0; cc < 16; ++cc) {
            int c = s * 16 + cc;
            float fv = fs[c * VPITCH + w + 1];
            fsq = fmaf(fv, fv, fsq);
        }
        rf[s][w] = fsq;
    }
    __syncthreads();
    if (t < 64) {
        float F = rf[0][t] + rf[1][t] + rf[2][t] + rf[3][t];
        sinv[t] = 1.f / (sqrtf(F) + 1e-8f);
    }
    __syncthreads();

    const int c = t & 63, s = t >> 6;
    #pragma unroll
    for (int it = 0; it < 16; ++it) {
        const int w = s * 16 + it;
        const float yv = vs[c * VPITCH + w] + vs[c * VPITCH + w + 1] + vs[c * VPITCH + w + 2];
        const float kv = fs[c * VPITCH + w + 1] * sinv[w];
        const size_t rowbase = ((size_t)(b * PPIX + h * 64 + w)) * CCH + c;
        __half hh, ll;
        split_h16(yv, hh, ll);
        g_Qh[rowbase] = hh; g_Ql[rowbase] = ll;
        hh = __float2half_rn(kv);
        g_Kh[rowbase] = hh;
        g_Kl[rowbase] = __float2half_rn((kv - __half2float(hh)) * KLSCALE);
    }
}

// ---------------------------------------------------------------------------
// attn v7 (fp16 + online max): q-tile 64, 8 warps = 4(qi) x 2(kj), 2 CTAs/SM.
// S = Qh*Kl'/256 + Qh*Kh + Ql*Kh  (96 MMAs, ~22-bit logits).
// Online per-row max M (per k-warp), O rescaled by 2^(M-Mn) per tile.
// PV = P(fp16, packed at 2^(s*log2e-M+14)) * Kh, single pass (32 MMAs).
// Epilogue merges the two k-warps with max reconciliation.
// ---------------------------------------------------------------------------
__global__ void __launch_bounds__(256, 2) attn_kernel(float* __restrict__ out) {
    extern __shared__ char smem[];
    const uint32_t sb = smem_u32(smem);

    const int b    = blockIdx.y;
    const int q0   = blockIdx.x * 64;
    const int t    = threadIdx.x;
    const int lane = t & 31;
    const int wid  = t >> 5;
    const int qi   = wid >> 1, kj = wid & 1;
    const int qo   = qi * 16,  ko = kj * 64;
    const int g    = lane >> 2, tq = lane & 3;

    // ---- persistent Q A-frags (hi/lo) ----
    uint32_t qa[2][4][4];
    #pragma unroll
    for (int hl = 0; hl < 2; ++hl) {
        const __half* Qsrc = hl ? g_Ql : g_Qh;
        const __half* r0 = Qsrc + (size_t)(b * PPIX + q0 + qo + g) * CCH;
        const __half* r8 = r0 + 8 * CCH;
        #pragma unroll
        for (int s = 0; s < 4; ++s) {
            int c0 = 16 * s + 2 * tq;
            qa[hl][s][0] = *(const uint32_t*)(r0 + c0);
            qa[hl][s][1] = *(const uint32_t*)(r8 + c0);
            qa[hl][s][2] = *(const uint32_t*)(r0 + c0 + 8);
            qa[hl][s][3] = *(const uint32_t*)(r8 + c0 + 8);
        }
    }

    float oacc[8][4];
    #pragma unroll
    for (int n = 0; n < 8; ++n)
        #pragma unroll
        for (int r = 0; r < 4; ++r) oacc[n][r] = 0.f;
    float lsum[2] = {0.f, 0.f};
    float M[2] = {-1e30f, -1e30f};     // running row max, log2 units

    const __half* gKh = g_Kh + (size_t)b * PPIX * CCH;
    const __half* gKl = g_Kl + (size_t)b * PPIX * CCH;

    load_tile(sb, gKh, gKl, 0, t);
    asm volatile("cp.async.commit_group;" ::: "memory");

    const uint32_t laneoff = (uint32_t)(((lane & 7) + 8 * ((lane >> 3) & 1)) * KPITCH
                                        + (lane >> 4) * 16);

    for (int kt = 0; kt < 32; ++kt) {
        __syncthreads();
        if (kt + 1 < 32)
            load_tile(sb + ((kt + 1) & 1) * BUF_BYTES, gKh, gKl, (kt + 1) * 128, t);
        asm volatile("cp.async.commit_group;" ::: "memory");
        asm volatile("cp.async.wait_group 1;" ::: "memory");
        __syncthreads();

        const uint32_t aH = sb + (uint32_t)(kt & 1) * BUF_BYTES;
        const uint32_t aL = aH + TILE_H;

        float sacc[8][4];
        #pragma unroll
        for (int j = 0; j < 8; ++j)
            #pragma unroll
            for (int r = 0; r < 4; ++r) sacc[j][r] = 0.f;

        // ---- Phase A: Qh * Kl' (scaled cross term) ----
        #pragma unroll
        for (int s = 0; s < 4; ++s) {
            #pragma unroll
            for (int jg = 0; jg < 2; ++jg) {
                uint32_t bl[4][2];
                #pragma unroll
                for (int j4 = 0; j4 < 4; ++j4) {
                    const int j = jg * 4 + j4;
                    const uint32_t o = (uint32_t)((ko + 8 * j + g) * KPITCH + 4 * tq + 32 * s);
                    bl[j4][0] = lds32(aL + o);
                    bl[j4][1] = lds32(aL + o + 16);
                }
                #pragma unroll
                for (int j4 = 0; j4 < 4; ++j4)
                    mma16816(sacc[jg * 4 + j4], qa[0][s], bl[j4][0], bl[j4][1]);
            }
        }
        #pragma unroll
        for (int j = 0; j < 8; ++j)
            #pragma unroll
            for (int r = 0; r < 4; ++r) sacc[j][r] *= KLINV;

        // ---- Phase B: Qh*Kh + Ql*Kh ----
        #pragma unroll
        for (int s = 0; s < 4; ++s) {
            #pragma unroll
            for (int jg = 0; jg < 2; ++jg) {
                uint32_t bh[4][2];
                #pragma unroll
                for (int j4 = 0; j4 < 4; ++j4) {
                    const int j = jg * 4 + j4;
                    const uint32_t o = (uint32_t)((ko + 8 * j + g) * KPITCH + 4 * tq + 32 * s);
                    bh[j4][0] = lds32(aH + o);
                    bh[j4][1] = lds32(aH + o + 16);
                }
                #pragma unroll
                for (int j4 = 0; j4 < 4; ++j4)
                    mma16816(sacc[jg * 4 + j4], qa[0][s], bh[j4][0], bh[j4][1]);
                #pragma unroll
                for (int j4 = 0; j4 < 4; ++j4)
                    mma16816(sacc[jg * 4 + j4], qa[1][s], bh[j4][0], bh[j4][1]);
            }
        }

        // ---- online max update ----
        float t0 = -1e30f, t1 = -1e30f;
        #pragma unroll
        for (int j = 0; j < 8; ++j) {
            t0 = fmaxf(t0, fmaxf(sacc[j][0], sacc[j][1]));
            t1 = fmaxf(t1, fmaxf(sacc[j][2], sacc[j][3]));
        }
        t0 = fmaxf(t0, __shfl_xor_sync(0xffffffffu, t0, 1));
        t0 = fmaxf(t0, __shfl_xor_sync(0xffffffffu, t0, 2));
        t1 = fmaxf(t1, __shfl_xor_sync(0xffffffffu, t1, 1));
        t1 = fmaxf(t1, __shfl_xor_sync(0xffffffffu, t1, 2));
        const float Mn0 = fmaxf(M[0], t0 * LOG2E);
        const float Mn1 = fmaxf(M[1], t1 * LOG2E);
        const float c0 = ex2(M[0] - Mn0);
        const float c1 = ex2(M[1] - Mn1);
        M[0] = Mn0; M[1] = Mn1;
        lsum[0] *= c0; lsum[1] *= c1;
        #pragma unroll
        for (int n = 0; n < 8; ++n) {
            oacc[n][0] *= c0; oacc[n][1] *= c0;
            oacc[n][2] *= c1; oacc[n][3] *= c1;
        }

        // ---- pack P (fp16, scale 2^PSH) ----
        uint32_t pah[4][4];
        const float sh0 = PSH - Mn0, sh1 = PSH - Mn1;
        #pragma unroll
        for (int j = 0; j < 8; ++j) {
            float p0 = ex2(fmaf(sacc[j][0], LOG2E, sh0));
            float p1 = ex2(fmaf(sacc[j][1], LOG2E, sh0));
            float p2 = ex2(fmaf(sacc[j][2], LOG2E, sh1));
            float p3 = ex2(fmaf(sacc[j][3], LOG2E, sh1));
            lsum[0] += p0 + p1;
            lsum[1] += p2 + p3;
            const int s2 = j >> 1, r = (j & 1) * 2;
            __half2 h01 = __floats2half2_rn(p0, p1);
            __half2 h23 = __floats2half2_rn(p2, p3);
            pah[s2][r]     = *(uint32_t*)&h01;
            pah[s2][r + 1] = *(uint32_t*)&h23;
        }

        // ---- O += P.Vh, single fp16 pass ----
        #pragma unroll
        for (int s2 = 0; s2 < 4; ++s2) {
            const uint32_t base = (uint32_t)((ko + 16 * s2) * KPITCH) + laneoff;
            #pragma unroll
            for (int jpg = 0; jpg < 2; ++jpg) {
                uint32_t bh0[4], bh1[4];
                ldsm4t(bh0, aH + base + (jpg * 2 + 0) * 32);
                ldsm4t(bh1, aH + base + (jpg * 2 + 1) * 32);
                const int jpA = jpg * 2, jpB = jpg * 2 + 1;
                mma16816(oacc[2 * jpA],     pah[s2], bh0[0], bh0[1]);
                mma16816(oacc[2 * jpA + 1], pah[s2], bh0[2], bh0[3]);
                mma16816(oacc[2 * jpB],     pah[s2], bh1[0], bh1[1]);
                mma16816(oacc[2 * jpB + 1], pah[s2], bh1[2], bh1[3]);
            }
        }
    }

    // ---- epilogue: quad-reduce lsum; merge k-warps with max reconciliation ----
    #pragma unroll
    for (int h = 0; h < 2; ++h) {
        lsum[h] += __shfl_xor_sync(0xffffffffu, lsum[h], 1);
        lsum[h] += __shfl_xor_sync(0xffffffffu, lsum[h], 2);
    }

    float* redO = (float*)smem;                    // [4 qi][32 lanes][33]
    float* redL = (float*)(smem + 17408);          // [64] row lsums
    float* redM = (float*)(smem + 17664);          // [64] row maxes
    float* stg  = (float*)(smem + 36864);          // [64 c][68 q]

    if (kj == 1) {
        float* dst = redO + (qi * 32 + lane) * 33;
        #pragma unroll
        for (int n = 0; n < 8; ++n)
            #pragma unroll
            for (int r = 0; r < 4; ++r)
                dst[n * 4 + r] = oacc[n][r];
        if (tq == 0) {
            redL[qi * 16 + g]     = lsum[0];
            redL[qi * 16 + 8 + g] = lsum[1];
            redM[qi * 16 + g]     = M[0];
            redM[qi * 16 + 8 + g] = M[1];
        }
    }
    __syncthreads();

    if (kj == 0) {
        const float* src = redO + (qi * 32 + lane) * 33;
        float fme[2], fot[2], inv[2];
        #pragma unroll
        for (int h = 0; h < 2; ++h) {
            const float Mo = redM[qi * 16 + 8 * h + g];
            const float lo = redL[qi * 16 + 8 * h + g];
            const float Mt = fmaxf(M[h], Mo);
            fme[h] = ex2(M[h] - Mt);
            fot[h] = ex2(Mo - Mt);
            inv[h] = 1.f / (lsum[h] * fme[h] + lo * fot[h]);
        }
        #pragma unroll
        for (int n = 0; n < 8; ++n)
            #pragma unroll
            for (int r = 0; r < 4; ++r) {
                const int h = r >> 1;
                float v = (oacc[n][r] * fme[h] + src[n * 4 + r] * fot[h]) * inv[h];
                int q = qo + g + ((r & 2) ? 8 : 0);
                int c = 8 * n + 2 * tq + (r & 1);
                stg[c * 68 + q] = v;
            }
    }
    __syncthreads();

    float* ob = out + (size_t)b * CCH * PPIX;
    #pragma unroll
    for (int it = 0; it < 4; ++it) {
        int i = t + 256 * it;
        int row = i >> 4, f4 = i & 15;
        float4 v = *(const float4*)(stg + row * 68 + f4 * 4);
        *(float4*)(ob + row * PPIX + q0 + 4 * f4) = v;
    }
}

// ---------------------------------------------------------------------------
extern "C" void kernel_launch(void* const* d_in, const int* in_sizes, int n_in,
                              void* d_out, int out_size) {
    const float* f = (const float*)d_in[0];   // foreground [4,64,64,64] fp32
    float* out = (float*)d_out;               // [4,64,64,64] fp32

    prep_kernel<<<dim3(64, 4), 256>>>(f);

    cudaFuncSetAttribute(attn_kernel, cudaFuncAttributeMaxDynamicSharedMemorySize, SMEM_TOTAL);
    attn_kernel<<<dim3(64, 4), 256, SMEM_TOTAL>>>(out);
}

// round 11
// speedup vs baseline: 2.3587x; 1.0314x over previous
#include <cuda_runtime.h>
#include <cuda_fp16.h>
#include <stdint.h>
#include <math.h>

// Problem constants: B=4, C=64, H=W=64, P=4096.
#define BATCH 4
#define CCH   64
#define PPIX  4096
#define LOG2E 1.4426950408889634f
#define PSH   14.0f                 // pack scale: p' = 2^(s*log2e - M + 14) <= 2^14
#define KLSCALE 256.0f
#define KLINV  0.00390625f

// ---------------------------------------------------------------------------
// Device scratch. fp16 split x = hi + lo (~22 bits). Kl stored *256 so its
// elements sit in fp16 normal range.
// ---------------------------------------------------------------------------
__device__ __half g_Qh[BATCH * PPIX * CCH];  // Y boxsum  [b][p][c]
__device__ __half g_Ql[BATCH * PPIX * CCH];
__device__ __half g_Kh[BATCH * PPIX * CCH];  // K-hat     [b][p][c]  (also V)
__device__ __half g_Kl[BATCH * PPIX * CCH];  // (K - Kh) * 256

// ---------------------------------------------------------------------------
// helpers (baseline PTX only: mma.sync / ldmatrix / cp.async)
// ---------------------------------------------------------------------------
__device__ __forceinline__ uint32_t smem_u32(const void* p) {
    uint32_t a;
    asm("{ .reg .u64 t; cvta.to.shared.u64 t, %1; cvt.u32.u64 %0, t; }" : "=r"(a) : "l"(p));
    return a;
}
__device__ __forceinline__ void ldsm4(uint32_t* r, uint32_t addr) {   // non-trans
    asm volatile("ldmatrix.sync.aligned.m8n8.x4.shared.b16 {%0,%1,%2,%3}, [%4];"
        : "=r"(r[0]), "=r"(r[1]), "=r"(r[2]), "=r"(r[3]) : "r"(addr));
}
__device__ __forceinline__ void ldsm4t(uint32_t* r, uint32_t addr) {  // trans
    asm volatile("ldmatrix.sync.aligned.m8n8.x4.trans.shared.b16 {%0,%1,%2,%3}, [%4];"
        : "=r"(r[0]), "=r"(r[1]), "=r"(r[2]), "=r"(r[3]) : "r"(addr));
}
__device__ __forceinline__ void mma16816(float* d, const uint32_t* a, uint32_t b0, uint32_t b1) {
    asm volatile(
        "mma.sync.aligned.m16n8k16.row.col.f32.f16.f16.f32 "
        "{%0,%1,%2,%3}, {%4,%5,%6,%7}, {%8,%9}, {%0,%1,%2,%3};"
        : "+f"(d[0]), "+f"(d[1]), "+f"(d[2]), "+f"(d[3])
        : "r"(a[0]), "r"(a[1]), "r"(a[2]), "r"(a[3]), "r"(b0), "r"(b1));
}
__device__ __forceinline__ float ex2(float x) {
    float r; asm("ex2.approx.ftz.f32 %0, %1;" : "=f"(r) : "f"(x)); return r;
}
__device__ __forceinline__ void split_h16(float x, __half& h, __half& l) {
    h = __float2half_rn(x);
    l = __float2half_rn(x - __half2float(h));
}

// K tile smem geometry: [128 k][64 c] fp16, row pitch 144B (128B data + 16B pad)
#define KPITCH    144
#define TILE_H    18432            // 128 * 144
#define BUF_BYTES 36864            // hi + lo
#define SMEM_TOTAL 73728           // two buffers (2 CTAs/SM -> 144KB/SM)

__device__ __forceinline__ void load_tile(uint32_t dbuf,
                                          const __half* gKh,
                                          const __half* gKl,
                                          int k0, int t) {
    #pragma unroll
    for (int c = 0; c < 4; ++c) {
        int idx = t + 256 * c;                 // 0..1023
        int row = idx >> 3, ch = idx & 7;
        uint32_t d = dbuf + row * KPITCH + ch * 16;
        const void* sh = gKh + (size_t)(k0 + row) * CCH + ch * 8;
        const void* sl = gKl + (size_t)(k0 + row) * CCH + ch * 8;
        asm volatile("cp.async.cg.shared.global [%0], [%1], 16;" :: "r"(d), "l"(sh));
        asm volatile("cp.async.cg.shared.global [%0], [%1], 16;" :: "r"(d + TILE_H), "l"(sl));
    }
}

// ---------------------------------------------------------------------------
// prep: one CTA per (h row, batch); emits fp16 hi/lo splits (Kl scaled x256).
// ---------------------------------------------------------------------------
#define VPITCH 67
__global__ void __launch_bounds__(256) prep_kernel(const float* __restrict__ f) {
    const int b = blockIdx.y;
    const int h = blockIdx.x;
    const int t = threadIdx.x;

    __shared__ float vs[CCH * VPITCH];
    __shared__ float fs[CCH * VPITCH];
    __shared__ float rf[4][64];
    __shared__ float sinv[64];

    const float* fb = f + (size_t)b * CCH * PPIX + h * 64;

    #pragma unroll
    for (int i = t; i < CCH * 64; i += 256) {
        int c = i >> 6, w = i & 63;
        const float* base = fb + (size_t)c * PPIX + w;
        float mid = base[0];
        float top = (h > 0)  ? base[-64] : 0.f;
        float bot = (h < 63) ? base[64]  : 0.f;
        vs[c * VPITCH + w + 1] = top + mid + bot;
        fs[c * VPITCH + w + 1] = mid;
    }
    if (t < CCH) { vs[t * VPITCH] = 0.f; vs[t * VPITCH + 65] = 0.f; }
    __syncthreads();

    {
        const int w = t & 63, s = t >> 6;
        float fsq = 0.f;
        #pragma unroll
        for (int cc = 0; cc < 16; ++cc) {
            int c = s * 16 + cc;
            float fv = fs[c * VPITCH + w + 1];
            fsq = fmaf(fv, fv, fsq);
        }
        rf[s][w] = fsq;
    }
    __syncthreads();
    if (t < 64) {
        float F = rf[0][t] + rf[1][t] + rf[2][t] + rf[3][t];
        sinv[t] = 1.f / (sqrtf(F) + 1e-8f);
    }
    __syncthreads();

    const int c = t & 63, s = t >> 6;
    #pragma unroll
    for (int it = 0; it < 16; ++it) {
        const int w = s * 16 + it;
        const float yv = vs[c * VPITCH + w] + vs[c * VPITCH + w + 1] + vs[c * VPITCH + w + 2];
        const float kv = fs[c * VPITCH + w + 1] * sinv[w];
        const size_t rowbase = ((size_t)(b * PPIX + h * 64 + w)) * CCH + c;
        __half hh, ll;
        split_h16(yv, hh, ll);
        g_Qh[rowbase] = hh; g_Ql[rowbase] = ll;
        hh = __float2half_rn(kv);
        g_Kh[rowbase] = hh;
        g_Kl[rowbase] = __float2half_rn((kv - __half2float(hh)) * KLSCALE);
    }
}

// ---------------------------------------------------------------------------
// attn v8 (fp16 + online max + ldmatrix S-loads):
// q-tile 64, 8 warps = 4(qi) x 2(kj), 2 CTAs/SM.
// S = Qh*Kl'/256 + Qh*Kh + Ql*Kh  (96 MMAs; B-frags via ldmatrix.x4).
// PV = P(fp16) * Kh, single pass (32 MMAs).
// ---------------------------------------------------------------------------
__global__ void __launch_bounds__(256, 2) attn_kernel(float* __restrict__ out) {
    extern __shared__ char smem[];
    const uint32_t sb = smem_u32(smem);

    const int b    = blockIdx.y;
    const int q0   = blockIdx.x * 64;
    const int t    = threadIdx.x;
    const int lane = t & 31;
    const int wid  = t >> 5;
    const int qi   = wid >> 1, kj = wid & 1;
    const int qo   = qi * 16,  ko = kj * 64;
    const int g    = lane >> 2, tq = lane & 3;

    // ---- persistent Q A-frags (hi/lo) ----
    uint32_t qa[2][4][4];
    #pragma unroll
    for (int hl = 0; hl < 2; ++hl) {
        const __half* Qsrc = hl ? g_Ql : g_Qh;
        const __half* r0 = Qsrc + (size_t)(b * PPIX + q0 + qo + g) * CCH;
        const __half* r8 = r0 + 8 * CCH;
        #pragma unroll
        for (int s = 0; s < 4; ++s) {
            int c0 = 16 * s + 2 * tq;
            qa[hl][s][0] = *(const uint32_t*)(r0 + c0);
            qa[hl][s][1] = *(const uint32_t*)(r8 + c0);
            qa[hl][s][2] = *(const uint32_t*)(r0 + c0 + 8);
            qa[hl][s][3] = *(const uint32_t*)(r8 + c0 + 8);
        }
    }

    float oacc[8][4];
    #pragma unroll
    for (int n = 0; n < 8; ++n)
        #pragma unroll
        for (int r = 0; r < 4; ++r) oacc[n][r] = 0.f;
    float lsum[2] = {0.f, 0.f};
    float M[2] = {-1e30f, -1e30f};     // running row max, log2 units

    const __half* gKh = g_Kh + (size_t)b * PPIX * CCH;
    const __half* gKl = g_Kl + (size_t)b * PPIX * CCH;

    load_tile(sb, gKh, gKl, 0, t);
    asm volatile("cp.async.commit_group;" ::: "memory");

    // ldmatrix per-thread offsets:
    //  S-phase (non-trans): lanes 0-7 -> (j4loc0,b0), 8-15 -> (j4loc0,b1),
    //                       16-23 -> (j4loc1,b0), 24-31 -> (j4loc1,b1)
    const uint32_t soff  = (uint32_t)((((lane >> 4) * 8) + (lane & 7)) * KPITCH
                                      + ((lane >> 3) & 1) * 16);
    //  PV-phase (trans) lane offset (unchanged from R10)
    const uint32_t laneoff = (uint32_t)(((lane & 7) + 8 * ((lane >> 3) & 1)) * KPITCH
                                        + (lane >> 4) * 16);

    for (int kt = 0; kt < 32; ++kt) {
        __syncthreads();
        if (kt + 1 < 32)
            load_tile(sb + ((kt + 1) & 1) * BUF_BYTES, gKh, gKl, (kt + 1) * 128, t);
        asm volatile("cp.async.commit_group;" ::: "memory");
        asm volatile("cp.async.wait_group 1;" ::: "memory");
        __syncthreads();

        const uint32_t aH = sb + (uint32_t)(kt & 1) * BUF_BYTES;
        const uint32_t aL = aH + TILE_H;
        const uint32_t sbaseH = aH + soff + (uint32_t)(ko * KPITCH);
        const uint32_t sbaseL = aL + soff + (uint32_t)(ko * KPITCH);

        float sacc[8][4];
        #pragma unroll
        for (int j = 0; j < 8; ++j)
            #pragma unroll
            for (int r = 0; r < 4; ++r) sacc[j][r] = 0.f;

        // ---- Phase A: Qh * Kl' (scaled cross term), ldmatrix B-frags ----
        #pragma unroll
        for (int s = 0; s < 4; ++s) {
            #pragma unroll
            for (int jg = 0; jg < 2; ++jg) {
                const uint32_t a0 = sbaseL + (uint32_t)(jg * 32 * KPITCH + 32 * s);
                uint32_t rA[4], rB[4];
                ldsm4(rA, a0);                          // j = jg*4 + 0,1
                ldsm4(rB, a0 + 16 * KPITCH);            // j = jg*4 + 2,3
                mma16816(sacc[jg * 4 + 0], qa[0][s], rA[0], rA[1]);
                mma16816(sacc[jg * 4 + 1], qa[0][s], rA[2], rA[3]);
                mma16816(sacc[jg * 4 + 2], qa[0][s], rB[0], rB[1]);
                mma16816(sacc[jg * 4 + 3], qa[0][s], rB[2], rB[3]);
            }
        }
        #pragma unroll
        for (int j = 0; j < 8; ++j)
            #pragma unroll
            for (int r = 0; r < 4; ++r) sacc[j][r] *= KLINV;

        // ---- Phase B: Qh*Kh + Ql*Kh, ldmatrix B-frags ----
        #pragma unroll
        for (int s = 0; s < 4; ++s) {
            #pragma unroll
            for (int jg = 0; jg < 2; ++jg) {
                const uint32_t a0 = sbaseH + (uint32_t)(jg * 32 * KPITCH + 32 * s);
                uint32_t rA[4], rB[4];
                ldsm4(rA, a0);
                ldsm4(rB, a0 + 16 * KPITCH);
                mma16816(sacc[jg * 4 + 0], qa[0][s], rA[0], rA[1]);
                mma16816(sacc[jg * 4 + 1], qa[0][s], rA[2], rA[3]);
                mma16816(sacc[jg * 4 + 2], qa[0][s], rB[0], rB[1]);
                mma16816(sacc[jg * 4 + 3], qa[0][s], rB[2], rB[3]);
                mma16816(sacc[jg * 4 + 0], qa[1][s], rA[0], rA[1]);
                mma16816(sacc[jg * 4 + 1], qa[1][s], rA[2], rA[3]);
                mma16816(sacc[jg * 4 + 2], qa[1][s], rB[0], rB[1]);
                mma16816(sacc[jg * 4 + 3], qa[1][s], rB[2], rB[3]);
            }
        }

        // ---- online max update ----
        float t0 = -1e30f, t1 = -1e30f;
        #pragma unroll
        for (int j = 0; j < 8; ++j) {
            t0 = fmaxf(t0, fmaxf(sacc[j][0], sacc[j][1]));
            t1 = fmaxf(t1, fmaxf(sacc[j][2], sacc[j][3]));
        }
        t0 = fmaxf(t0, __shfl_xor_sync(0xffffffffu, t0, 1));
        t0 = fmaxf(t0, __shfl_xor_sync(0xffffffffu, t0, 2));
        t1 = fmaxf(t1, __shfl_xor_sync(0xffffffffu, t1, 1));
        t1 = fmaxf(t1, __shfl_xor_sync(0xffffffffu, t1, 2));
        const float Mn0 = fmaxf(M[0], t0 * LOG2E);
        const float Mn1 = fmaxf(M[1], t1 * LOG2E);
        const float c0 = ex2(M[0] - Mn0);
        const float c1 = ex2(M[1] - Mn1);
        M[0] = Mn0; M[1] = Mn1;
        lsum[0] *= c0; lsum[1] *= c1;
        #pragma unroll
        for (int n = 0; n < 8; ++n) {
            oacc[n][0] *= c0; oacc[n][1] *= c0;
            oacc[n][2] *= c1; oacc[n][3] *= c1;
        }

        // ---- pack P (fp16, scale 2^PSH) ----
        uint32_t pah[4][4];
        const float sh0 = PSH - Mn0, sh1 = PSH - Mn1;
        #pragma unroll
        for (int j = 0; j < 8; ++j) {
            float p0 = ex2(fmaf(sacc[j][0], LOG2E, sh0));
            float p1 = ex2(fmaf(sacc[j][1], LOG2E, sh0));
            float p2 = ex2(fmaf(sacc[j][2], LOG2E, sh1));
            float p3 = ex2(fmaf(sacc[j][3], LOG2E, sh1));
            lsum[0] += p0 + p1;
            lsum[1] += p2 + p3;
            const int s2 = j >> 1, r = (j & 1) * 2;
            __half2 h01 = __floats2half2_rn(p0, p1);
            __half2 h23 = __floats2half2_rn(p2, p3);
            pah[s2][r]     = *(uint32_t*)&h01;
            pah[s2][r + 1] = *(uint32_t*)&h23;
        }

        // ---- O += P.Vh, single fp16 pass ----
        #pragma unroll
        for (int s2 = 0; s2 < 4; ++s2) {
            const uint32_t base = (uint32_t)((ko + 16 * s2) * KPITCH) + laneoff;
            #pragma unroll
            for (int jpg = 0; jpg < 2; ++jpg) {
                uint32_t bh0[4], bh1[4];
                ldsm4t(bh0, aH + base + (jpg * 2 + 0) * 32);
                ldsm4t(bh1, aH + base + (jpg * 2 + 1) * 32);
                const int jpA = jpg * 2, jpB = jpg * 2 + 1;
                mma16816(oacc[2 * jpA],     pah[s2], bh0[0], bh0[1]);
                mma16816(oacc[2 * jpA + 1], pah[s2], bh0[2], bh0[3]);
                mma16816(oacc[2 * jpB],     pah[s2], bh1[0], bh1[1]);
                mma16816(oacc[2 * jpB + 1], pah[s2], bh1[2], bh1[3]);
            }
        }
    }

    // ---- epilogue: quad-reduce lsum; merge k-warps with max reconciliation ----
    #pragma unroll
    for (int h = 0; h < 2; ++h) {
        lsum[h] += __shfl_xor_sync(0xffffffffu, lsum[h], 1);
        lsum[h] += __shfl_xor_sync(0xffffffffu, lsum[h], 2);
    }

    float* redO = (float*)smem;                    // [4 qi][32 lanes][33]
    float* redL = (float*)(smem + 17408);          // [64] row lsums
    float* redM = (float*)(smem + 17664);          // [64] row maxes
    float* stg  = (float*)(smem + 36864);          // [64 c][68 q]

    if (kj == 1) {
        float* dst = redO + (qi * 32 + lane) * 33;
        #pragma unroll
        for (int n = 0; n < 8; ++n)
            #pragma unroll
            for (int r = 0; r < 4; ++r)
                dst[n * 4 + r] = oacc[n][r];
        if (tq == 0) {
            redL[qi * 16 + g]     = lsum[0];
            redL[qi * 16 + 8 + g] = lsum[1];
            redM[qi * 16 + g]     = M[0];
            redM[qi * 16 + 8 + g] = M[1];
        }
    }
    __syncthreads();

    if (kj == 0) {
        const float* src = redO + (qi * 32 + lane) * 33;
        float fme[2], fot[2], inv[2];
        #pragma unroll
        for (int h = 0; h < 2; ++h) {
            const float Mo = redM[qi * 16 + 8 * h + g];
            const float lo = redL[qi * 16 + 8 * h + g];
            const float Mt = fmaxf(M[h], Mo);
            fme[h] = ex2(M[h] - Mt);
            fot[h] = ex2(Mo - Mt);
            inv[h] = 1.f / (lsum[h] * fme[h] + lo * fot[h]);
        }
        #pragma unroll
        for (int n = 0; n < 8; ++n)
            #pragma unroll
            for (int r = 0; r < 4; ++r) {
                const int h = r >> 1;
                float v = (oacc[n][r] * fme[h] + src[n * 4 + r] * fot[h]) * inv[h];
                int q = qo + g + ((r & 2) ? 8 : 0);
                int c = 8 * n + 2 * tq + (r & 1);
                stg[c * 68 + q] = v;
            }
    }
    __syncthreads();

    float* ob = out + (size_t)b * CCH * PPIX;
    #pragma unroll
    for (int it = 0; it < 4; ++it) {
        int i = t + 256 * it;
        int row = i >> 4, f4 = i & 15;
        float4 v = *(const float4*)(stg + row * 68 + f4 * 4);
        *(float4*)(ob + row * PPIX + q0 + 4 * f4) = v;
    }
}

// ---------------------------------------------------------------------------
extern "C" void kernel_launch(void* const* d_in, const int* in_sizes, int n_in,
                              void* d_out, int out_size) {
    const float* f = (const float*)d_in[0];   // foreground [4,64,64,64] fp32
    float* out = (float*)d_out;               // [4,64,64,64] fp32

    prep_kernel<<<dim3(64, 4), 256>>>(f);

    cudaFuncSetAttribute(attn_kernel, cudaFuncAttributeMaxDynamicSharedMemorySize, SMEM_TOTAL);
    attn_kernel<<<dim3(64, 4), 256, SMEM_TOTAL>>>(out);
}